// round 1
// baseline (speedup 1.0000x reference)
#include <cuda_runtime.h>
#include <cuda_bf16.h>

// ---------------- problem constants ----------------
#define NTOK   64          // tokens per window (8x8)
#define CDIM   256
#define HEADS  8
#define HD     32
#define PITCH  260         // smem row pitch (floats): 260*4=1040B, 16B aligned, stride%32=4 banks
#define NWIN   2048        // 8 images * 16 * 16 windows
#define CHW    4194304     // 256*128*128
#define SCALE  0.17677669529663687f   // 32^-0.5

// ---------------- precomputed device globals ----------------
__device__ float g_qT[32 * 512];           // [e][h*64+n]  (already * SCALE)
__device__ float g_biasT[HEADS * 64 * 64]; // [h][m][n]
__device__ float g_kvwT[256 * 512];        // [c][d]   (kv_w transposed)
__device__ float g_pwT[256 * 256];         // [c][d]   (proj_w transposed)

// ---------------- packed f32x2 helpers (Blackwell FFMA2) ----------------
__device__ __forceinline__ unsigned long long pk2(float x) {
    unsigned long long r;
    asm("mov.b64 %0, {%1, %1};" : "=l"(r) : "r"(__float_as_uint(x)));
    return r;
}
__device__ __forceinline__ float2 up2(unsigned long long v) {
    float2 f;
    asm("mov.b64 {%0, %1}, %2;" : "=f"(f.x), "=f"(f.y) : "l"(v));
    return f;
}
#define FMA2(d, a, b, c) \
    asm("fma.rn.f32x2 %0, %1, %2, %3;" : "=l"(d) : "l"(a), "l"(b), "l"(c))

// ---------------- setup kernel: tiny, runs once per launch ----------------
__global__ void setup_kernel(const float* __restrict__ emb,
                             const float* __restrict__ rpb,
                             const float* __restrict__ q_w,
                             const float* __restrict__ q_b,
                             const float* __restrict__ kv_w,
                             const float* __restrict__ proj_w) {
    int gid = blockIdx.x * blockDim.x + threadIdx.x;
    if (gid < 16384) {
        // q^T[e][h*64+n] = SCALE * (emb[n] . q_w[h*32+e] + q_b)
        int e  = gid >> 9;
        int hn = gid & 511;
        int h  = hn >> 6, n = hn & 63;
        int d  = h * 32 + e;
        const float* er = emb + n * 256;
        const float* wr = q_w + d * 256;
        float acc = q_b[d];
        #pragma unroll 4
        for (int c = 0; c < 256; c++) acc = fmaf(er[c], wr[c], acc);
        g_qT[gid] = acc * SCALE;
    } else if (gid < 16384 + 32768) {
        // bias^T[h][m][n] = rpb[relidx(n,m)*8 + h]
        int t = gid - 16384;
        int h = t >> 12;
        int m = (t >> 6) & 63;
        int n = t & 63;
        int r0 = (n >> 3) - (m >> 3) + 7;
        int r1 = (n & 7) - (m & 7) + 7;
        g_biasT[t] = rpb[(r0 * 15 + r1) * HEADS + h];
    } else if (gid < 16384 + 32768 + 131072) {
        int t = gid - 49152;              // c*512 + d
        int c = t >> 9, d = t & 511;
        g_kvwT[t] = kv_w[d * 256 + c];
    } else {                               // gid < 245760
        int t = gid - 180224;             // c*256 + d
        int c = t >> 8, d = t & 255;
        g_pwT[t] = proj_w[d * 256 + c];
    }
}

// ---------------- register-blocked fp32x2 GEMM pass ----------------
// C[64 x 256] = A[64 x 256](smem, PITCH) * B^T-slice(global, c-major) + bias
// 512 threads: ty=tid>>5 -> rows n0=4*ty ; tx=tid&31 -> cols {tx*4..+3, 128+tx*4..+3}
__device__ __forceinline__ void gemm_pass(
    const float* __restrict__ A,        // smem, pitch PITCH
    const float* __restrict__ Bt,       // global [c][ldB]
    int ldB, int dbase,
    const float* __restrict__ bias,     // global, 256 floats (already offset)
    float* dst, int dstPitch,           // smem (PITCH) or global (256)
    float* s_b, int tid) {

    const int ty = tid >> 5;
    const int tx = tid & 31;
    const int n0 = ty << 2;

    unsigned long long acc[4][4];
    #pragma unroll
    for (int i = 0; i < 4; i++)
        #pragma unroll
        for (int j = 0; j < 4; j++) acc[i][j] = 0ULL;   // bits(0,0) == (0.f,0.f)

    for (int kb = 0; kb < 16; kb++) {
        // stage B tile [16][256] (coalesced: rows of transposed weights)
        #pragma unroll
        for (int t = 0; t < 2; t++) {
            int li = tid + t * 512;            // float4 index over 1024
            int r  = li >> 6, c4 = li & 63;
            *(float4*)(s_b + r * 256 + c4 * 4) =
                *(const float4*)(Bt + (size_t)(kb * 16 + r) * ldB + dbase + c4 * 4);
        }
        __syncthreads();

        #pragma unroll
        for (int kk = 0; kk < 16; kk++) {
            int k = kb * 16 + kk;
            unsigned long long a0 = pk2(A[(n0 + 0) * PITCH + k]);   // broadcast LDS
            unsigned long long a1 = pk2(A[(n0 + 1) * PITCH + k]);
            unsigned long long a2 = pk2(A[(n0 + 2) * PITCH + k]);
            unsigned long long a3 = pk2(A[(n0 + 3) * PITCH + k]);
            const unsigned long long* b0 =
                (const unsigned long long*)(s_b + kk * 256 + tx * 4);
            const unsigned long long* b1 =
                (const unsigned long long*)(s_b + kk * 256 + 128 + tx * 4);
            unsigned long long bv0 = b0[0], bv1 = b0[1], bv2 = b1[0], bv3 = b1[1];
            FMA2(acc[0][0], a0, bv0, acc[0][0]);
            FMA2(acc[0][1], a0, bv1, acc[0][1]);
            FMA2(acc[0][2], a0, bv2, acc[0][2]);
            FMA2(acc[0][3], a0, bv3, acc[0][3]);
            FMA2(acc[1][0], a1, bv0, acc[1][0]);
            FMA2(acc[1][1], a1, bv1, acc[1][1]);
            FMA2(acc[1][2], a1, bv2, acc[1][2]);
            FMA2(acc[1][3], a1, bv3, acc[1][3]);
            FMA2(acc[2][0], a2, bv0, acc[2][0]);
            FMA2(acc[2][1], a2, bv1, acc[2][1]);
            FMA2(acc[2][2], a2, bv2, acc[2][2]);
            FMA2(acc[2][3], a2, bv3, acc[2][3]);
            FMA2(acc[3][0], a3, bv0, acc[3][0]);
            FMA2(acc[3][1], a3, bv1, acc[3][1]);
            FMA2(acc[3][2], a3, bv2, acc[3][2]);
            FMA2(acc[3][3], a3, bv3, acc[3][3]);
        }
        __syncthreads();
    }

    // epilogue: add bias, store two float4 per row
    float4 bA = *(const float4*)(bias + tx * 4);
    float4 bB = *(const float4*)(bias + 128 + tx * 4);
    #pragma unroll
    for (int i = 0; i < 4; i++) {
        float2 p0 = up2(acc[i][0]), p1 = up2(acc[i][1]);
        float2 p2 = up2(acc[i][2]), p3 = up2(acc[i][3]);
        float* drow = dst + (size_t)(n0 + i) * dstPitch;
        *(float4*)(drow + tx * 4) =
            make_float4(p0.x + bA.x, p0.y + bA.y, p1.x + bA.z, p1.y + bA.w);
        *(float4*)(drow + 128 + tx * 4) =
            make_float4(p2.x + bB.x, p2.y + bB.y, p3.x + bB.z, p3.y + bB.w);
    }
}

// ---------------- main fused kernel: one CTA per window ----------------
extern __shared__ float smem[];

__global__ void __launch_bounds__(512, 1)
win_attn_kernel(const float* __restrict__ x,
                const float* __restrict__ kv_b,
                const float* __restrict__ proj_b,
                float* __restrict__ out) {
    float* s_x = smem;               // 64*260 = 16640 f (also q^T stage, also s_o)
    float* s_k = smem + 16640;       // 16640 f
    float* s_v = smem + 33280;       // 16640 f
    float* s_b = smem + 49920;       // 16*256 = 4096 f
    const int tid = threadIdx.x;
    const int bw  = blockIdx.x;
    const int b   = bw >> 8;
    const int i   = (bw >> 4) & 15;
    const int j   = bw & 15;
    const float* xbase = x + (size_t)b * CHW + i * 262144 + j * 2048;

    // ---- phase A: load window [64 tok][256 ch] into smem ----
    #pragma unroll
    for (int t = 0; t < 8; t++) {
        int li = tid + t * 512;          // float4 index over 4096
        int n  = li >> 6, c4 = li & 63;
        int wi = n >> 3, wj = n & 7;
        float4 v = *(const float4*)(xbase + wi * 32768 + wj * 256 + c4 * 4);
        *(float4*)(s_x + n * PITCH + c4 * 4) = v;
    }
    __syncthreads();

    // ---- phase B: kv GEMM -> s_k, s_v ----
    gemm_pass(s_x, g_kvwT, 512, 0,   kv_b,       s_k, PITCH, s_b, tid);
    gemm_pass(s_x, g_kvwT, 512, 256, kv_b + 256, s_v, PITCH, s_b, tid);

    // ---- stage q^T over s_x (window data no longer needed) ----
    #pragma unroll
    for (int t = 0; t < 8; t++) {
        int li = tid + t * 512;          // float4 index over 4096 (16384 floats)
        *(float4*)(s_x + li * 4) = *(const float4*)(g_qT + li * 4);
    }
    __syncthreads();

    // ---- phase C: attention, one (head, token) row per thread ----
    const int h = tid >> 6;
    const int n = tid & 63;
    float s[64];
    #pragma unroll
    for (int m = 0; m < 64; m++) s[m] = 0.f;

    const float* kcol = s_k + h * 32;
    #pragma unroll 1
    for (int e = 0; e < 32; e++) {
        float qe = s_x[e * 512 + tid];           // q^T[e][h*64+n], conflict-free
        const float* kp = kcol + e;
        #pragma unroll
        for (int m = 0; m < 64; m++)
            s[m] = fmaf(qe, kp[m * PITCH], s[m]); // broadcast LDS
    }

    const float* bp = g_biasT + h * 4096 + n;    // [h][m][n], coalesced over n
    float mx = -1e30f;
    #pragma unroll
    for (int m = 0; m < 64; m++) { s[m] += bp[m * 64]; mx = fmaxf(mx, s[m]); }
    float sum = 0.f;
    #pragma unroll
    for (int m = 0; m < 64; m++) { s[m] = __expf(s[m] - mx); sum += s[m]; }
    float inv = 1.f / sum;
    #pragma unroll
    for (int m = 0; m < 64; m++) s[m] *= inv;

    __syncthreads();   // all q^T reads done -> s_x region becomes s_o

    #pragma unroll 1
    for (int eb = 0; eb < 2; eb++) {
        float o[16];
        #pragma unroll
        for (int e2 = 0; e2 < 16; e2++) o[e2] = 0.f;
        const float* vbase = s_v + h * 32 + eb * 16;
        #pragma unroll
        for (int m = 0; m < 64; m++) {
            float pv = s[m];
            const float* vp = vbase + m * PITCH;
            #pragma unroll
            for (int e2 = 0; e2 < 16; e2++)
                o[e2] = fmaf(pv, vp[e2], o[e2]);  // broadcast LDS
        }
        #pragma unroll
        for (int e2 = 0; e2 < 16; e2 += 4)
            *(float4*)(s_x + n * PITCH + h * 32 + eb * 16 + e2) =
                make_float4(o[e2], o[e2 + 1], o[e2 + 2], o[e2 + 3]);
    }
    __syncthreads();

    // ---- phase D: proj GEMM -> global out ----
    gemm_pass(s_x, g_pwT, 256, 0, proj_b,
              out + (size_t)bw * (NTOK * CDIM), 256, s_b, tid);
}

// ---------------- launcher ----------------
extern "C" void kernel_launch(void* const* d_in, const int* in_sizes, int n_in,
                              void* d_out, int out_size) {
    const float* x      = (const float*)d_in[0];
    const float* emb    = (const float*)d_in[1];
    const float* rpb    = (const float*)d_in[2];
    const float* q_w    = (const float*)d_in[3];
    const float* q_b    = (const float*)d_in[4];
    const float* kv_w   = (const float*)d_in[5];
    const float* kv_b   = (const float*)d_in[6];
    const float* proj_w = (const float*)d_in[7];
    const float* proj_b = (const float*)d_in[8];
    float* out = (float*)d_out;

    (void)in_sizes; (void)n_in; (void)out_size;

    cudaFuncSetAttribute(win_attn_kernel,
                         cudaFuncAttributeMaxDynamicSharedMemorySize, 216064);

    setup_kernel<<<480, 512>>>(emb, rpb, q_w, q_b, kv_w, proj_w);
    win_attn_kernel<<<NWIN, 512, 216064>>>(x, kv_b, proj_b, out);
}